// round 8
// baseline (speedup 1.0000x reference)
#include <cuda_runtime.h>
#include <math.h>
#include <stdint.h>

// ---------------------------------------------------------------------------
// FormationOptimizer: fully-connected GNN, N=512, 3 message-passing rounds.
// Edge layer0 factorized: A[i] + B[j] + dist*wd (fp32). Edge MLP GEMMs on
// tensor cores via mma.sync.m16n8k8 tf32, fp32 register accumulators.
// Register double-buffered global loads hide L2 latency across items.
// ---------------------------------------------------------------------------

#define NN 512
#define FD 64
#define H0D 128

__device__ float g_NF[NN * FD];
__device__ float g_DIST[NN * NN];
__device__ float g_A[NN * H0D];      // nf @ ew0[0:64]        [node][k]
__device__ float g_B[NN * H0D];      // nf @ ew0[64:128]+eb0  [node][k]
__device__ float g_AGG[NN * 32];

__device__ __forceinline__ uint32_t f2tf32(float x) {
    uint32_t u;
    asm("cvt.rna.tf32.f32 %0, %1;" : "=r"(u) : "f"(x));
    return u;
}
__device__ __forceinline__ void mma8(float* c, const uint32_t* a, const uint32_t* b) {
    asm volatile(
        "mma.sync.aligned.m16n8k8.row.col.f32.tf32.tf32.f32 "
        "{%0,%1,%2,%3}, {%4,%5,%6,%7}, {%8,%9}, {%0,%1,%2,%3};"
        : "+f"(c[0]), "+f"(c[1]), "+f"(c[2]), "+f"(c[3])
        : "r"(a[0]), "r"(a[1]), "r"(a[2]), "r"(a[3]), "r"(b[0]), "r"(b[1]));
}
__device__ __forceinline__ uint32_t ldsu(const float* p) {
    return __float_as_uint(*p);
}

// ---------------------------------------------------------------------------
__global__ void k_init_nf(const float* __restrict__ states,
                          const float* __restrict__ obj) {
    int idx = blockIdx.x * 256 + threadIdx.x;      // 128 x 256 = 32768
    int i = idx >> 6, c = idx & 63;
    g_NF[idx] = (c < 6) ? states[i * 6 + c] : obj[c - 6];
}

__global__ void k_init_dist(const float* __restrict__ states) {
    int i = blockIdx.x, t = threadIdx.x;
    float px = states[i * 6 + 0], py = states[i * 6 + 1], pz = states[i * 6 + 2];
    for (int j = t; j < NN; j += blockDim.x) {
        float dx = states[j * 6 + 0] - px;
        float dy = states[j * 6 + 1] - py;
        float dz = states[j * 6 + 2] - pz;
        g_DIST[i * NN + j] = sqrtf(dx * dx + dy * dy + dz * dz);
    }
}

// ---------------------------------------------------------------------------
// k_proj: A/B for iteration 0, zero g_AGG.
// ---------------------------------------------------------------------------
#define PROJ_SMEM (16384 + 512)
__global__ void __launch_bounds__(256) k_proj(const float* __restrict__ ew0,
                                              const float* __restrict__ eb0) {
    extern __shared__ float sm[];
    float* sE = sm;
    float* snf = sm + 16384;
    const int t = threadIdx.x;
    const int nb8 = blockIdx.x * 8;

    for (int q = 0; q < 16; q++)
        *(float4*)(sE + q * 1024 + t * 4) = *(const float4*)(ew0 + q * 1024 + t * 4);
    for (int q = 0; q < 2; q++)
        snf[q * 256 + t] = g_NF[nb8 * 64 + q * 256 + t];
    g_AGG[blockIdx.x * 256 + t] = 0.f;
    __syncthreads();

    const int nd = t >> 5;
    const int k4 = (t & 31) * 4;
    float4 a = make_float4(0.f, 0.f, 0.f, 0.f);
    float4 b = make_float4(0.f, 0.f, 0.f, 0.f);
#pragma unroll 4
    for (int c = 0; c < 64; c++) {
        float v = snf[nd * 64 + c];
        float4 wa = *(const float4*)(sE + c * 128 + k4);
        float4 wb = *(const float4*)(sE + (64 + c) * 128 + k4);
        a.x = fmaf(v, wa.x, a.x); a.y = fmaf(v, wa.y, a.y);
        a.z = fmaf(v, wa.z, a.z); a.w = fmaf(v, wa.w, a.w);
        b.x = fmaf(v, wb.x, b.x); b.y = fmaf(v, wb.y, b.y);
        b.z = fmaf(v, wb.z, b.z); b.w = fmaf(v, wb.w, b.w);
    }
    float4 e = *(const float4*)(eb0 + k4);
    b.x += e.x; b.y += e.y; b.z += e.z; b.w += e.w;
    *(float4*)(g_A + (nb8 + nd) * 128 + k4) = a;
    *(float4*)(g_B + (nb8 + nd) * 128 + k4) = b;
}

// ---------------------------------------------------------------------------
// k_edge: persistent mma.sync tf32 kernel. grid=296 (2 CTAs/SM), 256 threads.
// Items: 4096 = 512 receivers x 8 sender-tiles (64 senders each).
// ---------------------------------------------------------------------------
#define S_W1T 0
#define S_W2T 8448
#define S_H0  10624
#define S_H1  19072
#define S_WD  23424
#define S_B   23552     // 2 x 128 (double buffer)
#define E_SMEMF 23808   // 95232 bytes

#define NITEM 4096
#define EGRID 296

__device__ __forceinline__ void ldg_item(int item, float4* Ar, float& dr,
                                         float4& Br, int t)
{
    if (item >= NITEM) return;
    const int j = item >> 3;
    const int ibase = (item & 7) * 64;
    const int e = t & 63;
    const int kq = t >> 6;
    dr = __ldg(g_DIST + j * NN + ibase + e);
    const float4* Ap = (const float4*)(g_A + (ibase + e) * 128 + kq * 32);
#pragma unroll
    for (int q = 0; q < 8; q++) Ar[q] = __ldg(Ap + q);
    if (t < 32) Br = __ldg((const float4*)(g_B + j * 128) + t);
}

__device__ __forceinline__ void sts_H0(float* __restrict__ sH0,
                                       const float* __restrict__ sB,
                                       const float* __restrict__ swd,
                                       const float4* Ar, float dr, int t)
{
    const int e = t & 63;
    const int kq = t >> 6;
    float* dst = sH0 + e * 132 + kq * 32;
    const float4* Bp = (const float4*)(sB + kq * 32);
    const float4* Wp = (const float4*)(swd + kq * 32);
#pragma unroll
    for (int q = 0; q < 8; q++) {
        float4 a = Ar[q];
        float4 b = Bp[q];
        float4 w = Wp[q];
        float4 u;
        u.x = __uint_as_float(f2tf32(fmaxf(fmaf(dr, w.x, a.x + b.x), 0.f)));
        u.y = __uint_as_float(f2tf32(fmaxf(fmaf(dr, w.y, a.y + b.y), 0.f)));
        u.z = __uint_as_float(f2tf32(fmaxf(fmaf(dr, w.z, a.z + b.z), 0.f)));
        u.w = __uint_as_float(f2tf32(fmaxf(fmaf(dr, w.w, a.w + b.w), 0.f)));
        *(float4*)(dst + q * 4) = u;
    }
}

__global__ void __launch_bounds__(256, 2) k_edge(
    const float* __restrict__ ew0, const float* __restrict__ ew1,
    const float* __restrict__ eb1, const float* __restrict__ ew2,
    const float* __restrict__ eb2)
{
    extern __shared__ float sm[];
    float* sW1t = sm + S_W1T;
    float* sW2t = sm + S_W2T;
    float* sH0  = sm + S_H0;
    float* sH1  = sm + S_H1;
    float* swd  = sm + S_WD;
    float* sB2b = sm + S_B;

    const int t = threadIdx.x;
    const int lane = t & 31;
    const int w = t >> 5;
    const int ar = lane >> 2;
    const int ac = lane & 3;

    // ---- stage weights (transposed, tf32) once per CTA ----
    for (int idx = t; idx < 8192; idx += 256) {
        int k = idx >> 6, n = idx & 63;
        sW1t[n * 132 + k] = __uint_as_float(f2tf32(__ldg(ew1 + idx)));
    }
    for (int idx = t; idx < 2048; idx += 256) {
        int k2 = idx >> 5, m = idx & 31;
        sW2t[m * 68 + k2] = __uint_as_float(f2tf32(__ldg(ew2 + idx)));
    }
    if (t < 128) swd[t] = __ldg(ew0 + 128 * H0D + t);

    const int mw = (w & 1) * 32;
    const int nw = (w >> 1) * 16;
    const float e1b0 = __ldg(eb1 + nw + 2 * ac);
    const float e1b1 = __ldg(eb1 + nw + 2 * ac + 1);
    const float e1b2 = __ldg(eb1 + nw + 8 + 2 * ac);
    const float e1b3 = __ldg(eb1 + nw + 8 + 2 * ac + 1);

    const int mt = w & 3;
    const int nd2 = w >> 2;
    const float e2b0 = __ldg(eb2 + nd2 * 16 + 2 * ac);
    const float e2b1 = __ldg(eb2 + nd2 * 16 + 2 * ac + 1);
    const float e2b2 = __ldg(eb2 + nd2 * 16 + 8 + 2 * ac);
    const float e2b3 = __ldg(eb2 + nd2 * 16 + 8 + 2 * ac + 1);

    // ---- prologue: load item0, stage B0, build H0(item0), prefetch item1 ----
    float4 Ar[8];
    float dr = 0.f;
    float4 Br = make_float4(0.f, 0.f, 0.f, 0.f);
    int item = blockIdx.x;
    ldg_item(item, Ar, dr, Br, t);
    if (t < 32) *((float4*)sB2b + t) = Br;          // buffer 0
    __syncthreads();
    sts_H0(sH0, sB2b, swd, Ar, dr, t);
    ldg_item(item + EGRID, Ar, dr, Br, t);          // prefetch next
    __syncthreads();

    int par = 0;
    while (item < NITEM) {
        const int j = item >> 3;
        const int ibase = (item & 7) * 64;

        // ================= GEMM1: H1 = relu(H0 @ W1 + b1) =================
        {
            float acc[2][2][4];
#pragma unroll
            for (int mi = 0; mi < 2; mi++) {
                acc[mi][0][0] = e1b0; acc[mi][0][1] = e1b1;
                acc[mi][0][2] = e1b0; acc[mi][0][3] = e1b1;
                acc[mi][1][0] = e1b2; acc[mi][1][1] = e1b3;
                acc[mi][1][2] = e1b2; acc[mi][1][3] = e1b3;
            }
#pragma unroll 4
            for (int ks = 0; ks < 16; ks++) {
                const int k0 = ks * 8;
                uint32_t a[2][4], b[2][2];
#pragma unroll
                for (int mi = 0; mi < 2; mi++) {
                    const float* p = sH0 + (mw + mi * 16 + ar) * 132 + k0 + ac;
                    a[mi][0] = ldsu(p);
                    a[mi][1] = ldsu(p + 8 * 132);
                    a[mi][2] = ldsu(p + 4);
                    a[mi][3] = ldsu(p + 8 * 132 + 4);
                }
#pragma unroll
                for (int ni = 0; ni < 2; ni++) {
                    const float* p = sW1t + (nw + ni * 8 + ar) * 132 + k0 + ac;
                    b[ni][0] = ldsu(p);
                    b[ni][1] = ldsu(p + 4);
                }
#pragma unroll
                for (int mi = 0; mi < 2; mi++)
#pragma unroll
                    for (int ni = 0; ni < 2; ni++)
                        mma8(acc[mi][ni], a[mi], b[ni]);
            }
#pragma unroll
            for (int mi = 0; mi < 2; mi++) {
                const int row = mw + mi * 16 + ar;
#pragma unroll
                for (int ni = 0; ni < 2; ni++) {
                    const int col = nw + ni * 8 + 2 * ac;
                    float2 u0, u1;
                    u0.x = __uint_as_float(f2tf32(fmaxf(acc[mi][ni][0], 0.f)));
                    u0.y = __uint_as_float(f2tf32(fmaxf(acc[mi][ni][1], 0.f)));
                    u1.x = __uint_as_float(f2tf32(fmaxf(acc[mi][ni][2], 0.f)));
                    u1.y = __uint_as_float(f2tf32(fmaxf(acc[mi][ni][3], 0.f)));
                    *(float2*)(sH1 + row * 68 + col) = u0;
                    *(float2*)(sH1 + (row + 8) * 68 + col) = u1;
                }
            }
        }
        // stage B for next item (regs loaded one phase ago)
        if (t < 32) *((float4*)(sB2b + (par ^ 1) * 128) + t) = Br;
        __syncthreads();   // H1 + B(next) visible; H0 free

        // H0 for next item (A/d regs prefetched one phase ago)
        sts_H0(sH0, sB2b + (par ^ 1) * 128, swd, Ar, dr, t);

        // ================= GEMM2 + masked reduction (cur item) =============
        {
            float acc[2][4];
            acc[0][0] = e2b0; acc[0][1] = e2b1; acc[0][2] = e2b0; acc[0][3] = e2b1;
            acc[1][0] = e2b2; acc[1][1] = e2b3; acc[1][2] = e2b2; acc[1][3] = e2b3;
#pragma unroll
            for (int ks = 0; ks < 8; ks++) {
                const int k0 = ks * 8;
                uint32_t a[4], b[2][2];
                const float* p = sH1 + (mt * 16 + ar) * 68 + k0 + ac;
                a[0] = ldsu(p);
                a[1] = ldsu(p + 8 * 68);
                a[2] = ldsu(p + 4);
                a[3] = ldsu(p + 8 * 68 + 4);
#pragma unroll
                for (int ni = 0; ni < 2; ni++) {
                    const float* q = sW2t + (nd2 * 16 + ni * 8 + ar) * 68 + k0 + ac;
                    b[ni][0] = ldsu(q);
                    b[ni][1] = ldsu(q + 4);
                }
                mma8(acc[0], a, b[0]);
                mma8(acc[1], a, b[1]);
            }
            const int row0 = ibase + mt * 16 + ar;
            const int row1 = row0 + 8;
            const bool k0m = (row0 != j);
            const bool k1m = (row1 != j);
#pragma unroll
            for (int ni = 0; ni < 2; ni++) {
                float v0 = k0m ? fmaxf(acc[ni][0], 0.f) : 0.f;
                float v1 = k0m ? fmaxf(acc[ni][1], 0.f) : 0.f;
                float v2 = k1m ? fmaxf(acc[ni][2], 0.f) : 0.f;
                float v3 = k1m ? fmaxf(acc[ni][3], 0.f) : 0.f;
                float s0 = v0 + v2;
                float s1 = v1 + v3;
#pragma unroll
                for (int off = 4; off <= 16; off <<= 1) {
                    s0 += __shfl_xor_sync(0xffffffffu, s0, off);
                    s1 += __shfl_xor_sync(0xffffffffu, s1, off);
                }
                if (lane < 4) {
                    const int col = nd2 * 16 + ni * 8 + 2 * ac;
                    atomicAdd(g_AGG + j * 32 + col, s0);
                    atomicAdd(g_AGG + j * 32 + col + 1, s1);
                }
            }
        }

        // prefetch item+2G into regs (overlaps everything above next round)
        ldg_item(item + 2 * EGRID, Ar, dr, Br, t);
        __syncthreads();   // H0(next) visible; H1 free
        item += EGRID;
        par ^= 1;
    }
}

// ---------------------------------------------------------------------------
// k_node: 128 CTAs x 4 nodes, 256 threads. No weight staging (L1-cached LDG).
// Node MLP + residual, fused projection (A/B for next edge pass), zero g_AGG.
// ---------------------------------------------------------------------------
__global__ void __launch_bounds__(256) k_node(
    const float* __restrict__ nw0, const float* __restrict__ nb0,
    const float* __restrict__ nw1, const float* __restrict__ nb1,
    const float* __restrict__ nw2, const float* __restrict__ nb2,
    const float* __restrict__ nwo, const float* __restrict__ nbo,
    const float* __restrict__ ew0, const float* __restrict__ eb0)
{
    __shared__ float sy[4 * 96], sh0[4 * 128], sh1[4 * 64], sh2[4 * 32], sNF[4 * 64];
    const int t = threadIdx.x;
    const int nb4 = blockIdx.x * 4;

    // y = [nf | agg], 384 floats (strided: blockDim is 256!)
    for (int idx = t; idx < 384; idx += 256) {
        int nd = idx / 96, c = idx % 96;
        sy[idx] = (c < 64) ? g_NF[(nb4 + nd) * 64 + c]
                           : g_AGG[(nb4 + nd) * 32 + (c - 64)];
    }
    __syncthreads();
    // zero this CTA's g_AGG slice for the next edge pass (AFTER all reads)
    if (t < 128) g_AGG[blockIdx.x * 128 + t] = 0.f;

    // layer 0: 96 -> 128   (4 nodes x 128 outs = 512 = 256 thr x 2)
    {
        const int nd = t >> 6;
        const int o2 = (t & 63) * 2;
        float2 acc = *(const float2*)(nb0 + o2);
#pragma unroll 8
        for (int c = 0; c < 96; c++) {
            float v = sy[nd * 96 + c];
            float2 wv = __ldg((const float2*)(nw0 + c * 128 + o2));
            acc.x = fmaf(v, wv.x, acc.x);
            acc.y = fmaf(v, wv.y, acc.y);
        }
        sh0[nd * 128 + o2]     = fmaxf(acc.x, 0.f);
        sh0[nd * 128 + o2 + 1] = fmaxf(acc.y, 0.f);
    }
    __syncthreads();
    // layer 1: 128 -> 64   (4 x 64 = 256 outs)
    {
        const int nd = t >> 6;
        const int o = t & 63;
        float acc = __ldg(nb1 + o);
#pragma unroll 8
        for (int c = 0; c < 128; c++)
            acc = fmaf(sh0[nd * 128 + c], __ldg(nw1 + c * 64 + o), acc);
        sh1[nd * 64 + o] = fmaxf(acc, 0.f);
    }
    __syncthreads();
    // layer 2: 64 -> 32    (4 x 32 = 128 outs)
    if (t < 128) {
        const int nd = t >> 5;
        const int o = t & 31;
        float acc = __ldg(nb2 + o);
#pragma unroll 8
        for (int c = 0; c < 64; c++)
            acc = fmaf(sh1[nd * 64 + c], __ldg(nw2 + c * 32 + o), acc);
        sh2[nd * 32 + o] = fmaxf(acc, 0.f);
    }
    __syncthreads();
    // output: 32 -> 64, residual
    {
        const int nd = t >> 6;
        const int o = t & 63;
        float acc = __ldg(nbo + o);
#pragma unroll 8
        for (int c = 0; c < 32; c++)
            acc = fmaf(sh2[nd * 32 + c], __ldg(nwo + c * 64 + o), acc);
        float y = sy[nd * 96 + o] + acc;
        g_NF[(nb4 + nd) * 64 + o] = y;
        sNF[nd * 64 + o] = y;
    }
    __syncthreads();
    // fused projection: A = nf@ew0[0:64], B = nf@ew0[64:128]+eb0
    {
        const int nd = t >> 6;
        const int k2 = (t & 63) * 2;
        float2 a = make_float2(0.f, 0.f);
        float2 b = make_float2(0.f, 0.f);
#pragma unroll 8
        for (int c = 0; c < 64; c++) {
            float v = sNF[nd * 64 + c];
            float2 wa = __ldg((const float2*)(ew0 + c * 128 + k2));
            float2 wb = __ldg((const float2*)(ew0 + (64 + c) * 128 + k2));
            a.x = fmaf(v, wa.x, a.x); a.y = fmaf(v, wa.y, a.y);
            b.x = fmaf(v, wb.x, b.x); b.y = fmaf(v, wb.y, b.y);
        }
        float2 e = __ldg((const float2*)(eb0 + k2));
        b.x += e.x; b.y += e.y;
        const int node = nb4 + nd;
        *(float2*)(g_A + node * 128 + k2) = a;
        *(float2*)(g_B + node * 128 + k2) = b;
    }
}

// ---------------------------------------------------------------------------
__global__ void k_read(const float* __restrict__ rw, const float* __restrict__ rb,
                       float* __restrict__ out)
{
    int jn = blockIdx.x * blockDim.x + threadIdx.x;
    if (jn >= NN) return;
    float a0 = rb[0], a1 = rb[1], a2 = rb[2];
#pragma unroll
    for (int c = 0; c < 64; c++) {
        float v = g_NF[jn * FD + c];
        a0 = fmaf(v, rw[c * 3 + 0], a0);
        a1 = fmaf(v, rw[c * 3 + 1], a1);
        a2 = fmaf(v, rw[c * 3 + 2], a2);
    }
    out[jn * 3 + 0] = a0;
    out[jn * 3 + 1] = a1;
    out[jn * 3 + 2] = a2;
}

// ---------------------------------------------------------------------------
extern "C" void kernel_launch(void* const* d_in, const int* in_sizes, int n_in,
                              void* d_out, int out_size)
{
    const float* states = (const float*)d_in[0];
    const float* obj    = (const float*)d_in[1];
    const float* ew0 = (const float*)d_in[2];
    const float* eb0 = (const float*)d_in[3];
    const float* ew1 = (const float*)d_in[4];
    const float* eb1 = (const float*)d_in[5];
    const float* ew2 = (const float*)d_in[6];
    const float* eb2 = (const float*)d_in[7];
    const float* nw0 = (const float*)d_in[8];
    const float* nb0 = (const float*)d_in[9];
    const float* nw1 = (const float*)d_in[10];
    const float* nb1 = (const float*)d_in[11];
    const float* nw2 = (const float*)d_in[12];
    const float* nb2 = (const float*)d_in[13];
    const float* nwo = (const float*)d_in[14];
    const float* nbo = (const float*)d_in[15];
    const float* rw  = (const float*)d_in[16];
    const float* rb  = (const float*)d_in[17];
    float* out = (float*)d_out;

    cudaFuncSetAttribute(k_edge, cudaFuncAttributeMaxDynamicSharedMemorySize,
                         E_SMEMF * (int)sizeof(float));
    cudaFuncSetAttribute(k_proj, cudaFuncAttributeMaxDynamicSharedMemorySize,
                         PROJ_SMEM * (int)sizeof(float));

    // launch order puts the 2nd k_edge at index 5 (ncu -s 5 -c 1 capture slot)
    k_init_nf<<<128, 256>>>(states, obj);
    k_init_dist<<<NN, 256>>>(states);
    k_proj<<<64, 256, PROJ_SMEM * (int)sizeof(float)>>>(ew0, eb0);
    for (int it = 0; it < 3; it++) {
        k_edge<<<EGRID, 256, E_SMEMF * (int)sizeof(float)>>>(ew0, ew1, eb1, ew2, eb2);
        k_node<<<128, 256>>>(nw0, nb0, nw1, nb1, nw2, nb2, nwo, nbo, ew0, eb0);
    }
    k_read<<<4, 128>>>(rw, rb, out);
}

// round 9
// speedup vs baseline: 1.1543x; 1.1543x over previous
#include <cuda_runtime.h>
#include <cuda_fp16.h>
#include <math.h>
#include <stdint.h>

// ---------------------------------------------------------------------------
// FormationOptimizer: fully-connected GNN, N=512, 3 message-passing rounds.
// Edge layer0 factorized: A[i] + B[j] + dist*wd (fp32). Edge MLP GEMMs on
// tensor cores via mma.sync.m16n8k16 fp16 (same 11-bit significand as tf32),
// fp32 register accumulators; bias/relu/mask/reduce in-register.
// ---------------------------------------------------------------------------

#define NN 512
#define FD 64
#define H0D 128

__device__ float g_NF[NN * FD];
__device__ float g_DIST[NN * NN];
__device__ float g_A[NN * H0D];      // nf @ ew0[0:64]        [node][k]
__device__ float g_B[NN * H0D];      // nf @ ew0[64:128]+eb0  [node][k]
__device__ float g_AGG[NN * 32];

__device__ __forceinline__ uint32_t pack_h2(float lo, float hi) {
    __half2 h = __floats2half2_rn(lo, hi);
    return *(uint32_t*)&h;
}
__device__ __forceinline__ void mma16(float* c, const uint32_t* a, const uint32_t* b) {
    asm volatile(
        "mma.sync.aligned.m16n8k16.row.col.f32.f16.f16.f32 "
        "{%0,%1,%2,%3}, {%4,%5,%6,%7}, {%8,%9}, {%0,%1,%2,%3};"
        : "+f"(c[0]), "+f"(c[1]), "+f"(c[2]), "+f"(c[3])
        : "r"(a[0]), "r"(a[1]), "r"(a[2]), "r"(a[3]), "r"(b[0]), "r"(b[1]));
}

// ---------------------------------------------------------------------------
__global__ void k_init_nf(const float* __restrict__ states,
                          const float* __restrict__ obj) {
    int idx = blockIdx.x * 256 + threadIdx.x;      // 128 x 256 = 32768
    int i = idx >> 6, c = idx & 63;
    g_NF[idx] = (c < 6) ? states[i * 6 + c] : obj[c - 6];
}

__global__ void k_init_dist(const float* __restrict__ states) {
    int i = blockIdx.x, t = threadIdx.x;
    float px = states[i * 6 + 0], py = states[i * 6 + 1], pz = states[i * 6 + 2];
    for (int j = t; j < NN; j += blockDim.x) {
        float dx = states[j * 6 + 0] - px;
        float dy = states[j * 6 + 1] - py;
        float dz = states[j * 6 + 2] - pz;
        g_DIST[i * NN + j] = sqrtf(dx * dx + dy * dy + dz * dz);
    }
}

// ---------------------------------------------------------------------------
// k_proj: A/B for iteration 0, zero g_AGG.
// ---------------------------------------------------------------------------
#define PROJ_SMEM (16384 + 512)
__global__ void __launch_bounds__(256) k_proj(const float* __restrict__ ew0,
                                              const float* __restrict__ eb0) {
    extern __shared__ float sm[];
    float* sE = sm;
    float* snf = sm + 16384;
    const int t = threadIdx.x;
    const int nb8 = blockIdx.x * 8;

    for (int q = 0; q < 16; q++)
        *(float4*)(sE + q * 1024 + t * 4) = *(const float4*)(ew0 + q * 1024 + t * 4);
    for (int q = 0; q < 2; q++)
        snf[q * 256 + t] = g_NF[nb8 * 64 + q * 256 + t];
    g_AGG[blockIdx.x * 256 + t] = 0.f;
    __syncthreads();

    const int nd = t >> 5;
    const int k4 = (t & 31) * 4;
    float4 a = make_float4(0.f, 0.f, 0.f, 0.f);
    float4 b = make_float4(0.f, 0.f, 0.f, 0.f);
#pragma unroll 4
    for (int c = 0; c < 64; c++) {
        float v = snf[nd * 64 + c];
        float4 wa = *(const float4*)(sE + c * 128 + k4);
        float4 wb = *(const float4*)(sE + (64 + c) * 128 + k4);
        a.x = fmaf(v, wa.x, a.x); a.y = fmaf(v, wa.y, a.y);
        a.z = fmaf(v, wa.z, a.z); a.w = fmaf(v, wa.w, a.w);
        b.x = fmaf(v, wb.x, b.x); b.y = fmaf(v, wb.y, b.y);
        b.z = fmaf(v, wb.z, b.z); b.w = fmaf(v, wb.w, b.w);
    }
    float4 e = *(const float4*)(eb0 + k4);
    b.x += e.x; b.y += e.y; b.z += e.z; b.w += e.w;
    *(float4*)(g_A + (nb8 + nd) * 128 + k4) = a;
    *(float4*)(g_B + (nb8 + nd) * 128 + k4) = b;
}

// ---------------------------------------------------------------------------
// k_edge: persistent mma.sync fp16 kernel. grid=296 (2 CTAs/SM), 256 threads.
// Items: 4096 = 512 receivers x 8 sender-tiles (64 senders each).
// smem in 4-byte words: W1t[64][68] | W2t[32][36] | H0[64][68] | H1[64][36]
//   (each word = 2 fp16, k-pair packed) | wd 128 f32 | B 2x128 f32
// ---------------------------------------------------------------------------
#define S_W1T 0
#define S_W2T 4352
#define S_H0  5504
#define S_H1  9856
#define S_WD  12160
#define S_B   12288
#define E_SMEMW 12544    // words -> 50176 bytes

#define NITEM 4096
#define EGRID 296

__device__ __forceinline__ void ldg_item(int item, float4* Ar, float& dr,
                                         float4& Br, int t)
{
    if (item >= NITEM) return;
    const int j = item >> 3;
    const int ibase = (item & 7) * 64;
    const int e = t & 63;
    const int kq = t >> 6;
    dr = __ldg(g_DIST + j * NN + ibase + e);
    const float4* Ap = (const float4*)(g_A + (ibase + e) * 128 + kq * 32);
#pragma unroll
    for (int q = 0; q < 8; q++) Ar[q] = __ldg(Ap + q);
    if (t < 32) Br = __ldg((const float4*)(g_B + j * 128) + t);
}

// H0[e][k] = relu(A[i][k] + B[j][k] + d*wd[k]) -> fp16 word pairs
__device__ __forceinline__ void sts_H0(uint32_t* __restrict__ sH0w,
                                       const float* __restrict__ sB,
                                       const float* __restrict__ swd,
                                       const float4* Ar, float dr, int t)
{
    const int e = t & 63;
    const int kq = t >> 6;
    uint32_t* dst = sH0w + e * 68 + kq * 16;
    const float4* Bp = (const float4*)(sB + kq * 32);
    const float4* Wp = (const float4*)(swd + kq * 32);
#pragma unroll
    for (int q = 0; q < 4; q++) {
        float4 a0 = Ar[2 * q],     a1 = Ar[2 * q + 1];
        float4 b0 = Bp[2 * q],     b1 = Bp[2 * q + 1];
        float4 w0 = Wp[2 * q],     w1 = Wp[2 * q + 1];
        float h0 = fmaxf(fmaf(dr, w0.x, a0.x + b0.x), 0.f);
        float h1 = fmaxf(fmaf(dr, w0.y, a0.y + b0.y), 0.f);
        float h2 = fmaxf(fmaf(dr, w0.z, a0.z + b0.z), 0.f);
        float h3 = fmaxf(fmaf(dr, w0.w, a0.w + b0.w), 0.f);
        float h4 = fmaxf(fmaf(dr, w1.x, a1.x + b1.x), 0.f);
        float h5 = fmaxf(fmaf(dr, w1.y, a1.y + b1.y), 0.f);
        float h6 = fmaxf(fmaf(dr, w1.z, a1.z + b1.z), 0.f);
        float h7 = fmaxf(fmaf(dr, w1.w, a1.w + b1.w), 0.f);
        uint4 u;
        u.x = pack_h2(h0, h1);
        u.y = pack_h2(h2, h3);
        u.z = pack_h2(h4, h5);
        u.w = pack_h2(h6, h7);
        *(uint4*)(dst + q * 4) = u;
    }
}

__global__ void __launch_bounds__(256, 2) k_edge(
    const float* __restrict__ ew0, const float* __restrict__ ew1,
    const float* __restrict__ eb1, const float* __restrict__ ew2,
    const float* __restrict__ eb2)
{
    extern __shared__ uint32_t smw[];
    uint32_t* sW1tw = smw + S_W1T;
    uint32_t* sW2tw = smw + S_W2T;
    uint32_t* sH0w  = smw + S_H0;
    uint32_t* sH1w  = smw + S_H1;
    float* swd  = (float*)(smw + S_WD);
    float* sB2b = (float*)(smw + S_B);

    const int t = threadIdx.x;
    const int lane = t & 31;
    const int w = t >> 5;
    const int ar = lane >> 2;
    const int ac = lane & 3;

    // ---- stage weights (transposed, fp16 word pairs) once per CTA ----
    for (int idx = t; idx < 4096; idx += 256) {
        int n = idx >> 6, wk = idx & 63;                 // word wk = k pair (2wk, 2wk+1)
        sW1tw[n * 68 + wk] = pack_h2(__ldg(ew1 + (2 * wk) * 64 + n),
                                     __ldg(ew1 + (2 * wk + 1) * 64 + n));
    }
    for (int idx = t; idx < 1024; idx += 256) {
        int m = idx >> 5, wk = idx & 31;
        sW2tw[m * 36 + wk] = pack_h2(__ldg(ew2 + (2 * wk) * 32 + m),
                                     __ldg(ew2 + (2 * wk + 1) * 32 + m));
    }
    if (t < 128) swd[t] = __ldg(ew0 + 128 * H0D + t);

    // GEMM1 warp tile: edges [mw, mw+32), cols [nw, nw+16)
    const int mw = (w & 1) * 32;
    const int nw = (w >> 1) * 16;
    const float e1b0 = __ldg(eb1 + nw + 2 * ac);
    const float e1b1 = __ldg(eb1 + nw + 2 * ac + 1);
    const float e1b2 = __ldg(eb1 + nw + 8 + 2 * ac);
    const float e1b3 = __ldg(eb1 + nw + 8 + 2 * ac + 1);

    // GEMM2 warp tile: edges [16*mt, +16), cols [16*nd2, +16)
    const int mt = w & 3;
    const int nd2 = w >> 2;
    const float e2b0 = __ldg(eb2 + nd2 * 16 + 2 * ac);
    const float e2b1 = __ldg(eb2 + nd2 * 16 + 2 * ac + 1);
    const float e2b2 = __ldg(eb2 + nd2 * 16 + 8 + 2 * ac);
    const float e2b3 = __ldg(eb2 + nd2 * 16 + 8 + 2 * ac + 1);

    // ---- prologue ----
    float4 Ar[8];
    float dr = 0.f;
    float4 Br = make_float4(0.f, 0.f, 0.f, 0.f);
    int item = blockIdx.x;
    ldg_item(item, Ar, dr, Br, t);
    if (t < 32) *((float4*)sB2b + t) = Br;
    __syncthreads();
    sts_H0(sH0w, sB2b, swd, Ar, dr, t);
    ldg_item(item + EGRID, Ar, dr, Br, t);
    __syncthreads();

    int par = 0;
    while (item < NITEM) {
        const int j = item >> 3;
        const int ibase = (item & 7) * 64;

        // ================= GEMM1: H1 = relu(H0 @ W1 + b1), fp16 k=16 ========
        {
            float acc[2][2][4];
#pragma unroll
            for (int mi = 0; mi < 2; mi++) {
                acc[mi][0][0] = e1b0; acc[mi][0][1] = e1b1;
                acc[mi][0][2] = e1b0; acc[mi][0][3] = e1b1;
                acc[mi][1][0] = e1b2; acc[mi][1][1] = e1b3;
                acc[mi][1][2] = e1b2; acc[mi][1][3] = e1b3;
            }
#pragma unroll
            for (int ks = 0; ks < 8; ks++) {
                const int kw = ks * 8;
                uint32_t a[2][4], b[2][2];
#pragma unroll
                for (int mi = 0; mi < 2; mi++) {
                    const uint32_t* p = sH0w + (mw + mi * 16 + ar) * 68 + kw + ac;
                    a[mi][0] = p[0];
                    a[mi][1] = p[8 * 68];
                    a[mi][2] = p[4];
                    a[mi][3] = p[8 * 68 + 4];
                }
#pragma unroll
                for (int ni = 0; ni < 2; ni++) {
                    const uint32_t* p = sW1tw + (nw + ni * 8 + ar) * 68 + kw + ac;
                    b[ni][0] = p[0];
                    b[ni][1] = p[4];
                }
#pragma unroll
                for (int mi = 0; mi < 2; mi++)
#pragma unroll
                    for (int ni = 0; ni < 2; ni++)
                        mma16(acc[mi][ni], a[mi], b[ni]);
            }
            // epilogue: relu -> fp16 word pairs into H1
#pragma unroll
            for (int mi = 0; mi < 2; mi++) {
                const int row = mw + mi * 16 + ar;
#pragma unroll
                for (int ni = 0; ni < 2; ni++) {
                    const int wcol = (nw >> 1) + ni * 4 + ac;
                    sH1w[row * 36 + wcol] =
                        pack_h2(fmaxf(acc[mi][ni][0], 0.f), fmaxf(acc[mi][ni][1], 0.f));
                    sH1w[(row + 8) * 36 + wcol] =
                        pack_h2(fmaxf(acc[mi][ni][2], 0.f), fmaxf(acc[mi][ni][3], 0.f));
                }
            }
        }
        // stage B for next item (regs loaded one phase ago)
        if (t < 32) *((float4*)(sB2b + (par ^ 1) * 128) + t) = Br;
        __syncthreads();   // H1 + B(next) visible; H0 free

        // H0 for next item (A/d regs prefetched one phase ago)
        sts_H0(sH0w, sB2b + (par ^ 1) * 128, swd, Ar, dr, t);

        // ================= GEMM2 + masked reduction (cur item) ==============
        {
            float acc[2][4];
            acc[0][0] = e2b0; acc[0][1] = e2b1; acc[0][2] = e2b0; acc[0][3] = e2b1;
            acc[1][0] = e2b2; acc[1][1] = e2b3; acc[1][2] = e2b2; acc[1][3] = e2b3;
#pragma unroll
            for (int ks = 0; ks < 4; ks++) {
                const int kw = ks * 8;
                uint32_t a[4], b[2][2];
                const uint32_t* p = sH1w + (mt * 16 + ar) * 36 + kw + ac;
                a[0] = p[0];
                a[1] = p[8 * 36];
                a[2] = p[4];
                a[3] = p[8 * 36 + 4];
#pragma unroll
                for (int ni = 0; ni < 2; ni++) {
                    const uint32_t* q = sW2tw + (nd2 * 16 + ni * 8 + ar) * 36 + kw + ac;
                    b[ni][0] = q[0];
                    b[ni][1] = q[4];
                }
                mma16(acc[0], a, b[0]);
                mma16(acc[1], a, b[1]);
            }
            const int row0 = ibase + mt * 16 + ar;
            const int row1 = row0 + 8;
            const bool k0m = (row0 != j);
            const bool k1m = (row1 != j);
#pragma unroll
            for (int ni = 0; ni < 2; ni++) {
                float v0 = k0m ? fmaxf(acc[ni][0], 0.f) : 0.f;
                float v1 = k0m ? fmaxf(acc[ni][1], 0.f) : 0.f;
                float v2 = k1m ? fmaxf(acc[ni][2], 0.f) : 0.f;
                float v3 = k1m ? fmaxf(acc[ni][3], 0.f) : 0.f;
                float s0 = v0 + v2;
                float s1 = v1 + v3;
#pragma unroll
                for (int off = 4; off <= 16; off <<= 1) {
                    s0 += __shfl_xor_sync(0xffffffffu, s0, off);
                    s1 += __shfl_xor_sync(0xffffffffu, s1, off);
                }
                if (lane < 4) {
                    const int col = nd2 * 16 + ni * 8 + 2 * ac;
                    atomicAdd(g_AGG + j * 32 + col, s0);
                    atomicAdd(g_AGG + j * 32 + col + 1, s1);
                }
            }
        }

        // prefetch item+2G into regs
        ldg_item(item + 2 * EGRID, Ar, dr, Br, t);
        __syncthreads();   // H0(next) visible; H1 free
        item += EGRID;
        par ^= 1;
    }
}

// ---------------------------------------------------------------------------
// k_node: 128 CTAs x 4 nodes, 256 threads. Node MLP + residual, fused
// projection (A/B for next edge pass), zero g_AGG.
// ---------------------------------------------------------------------------
__global__ void __launch_bounds__(256) k_node(
    const float* __restrict__ nw0, const float* __restrict__ nb0,
    const float* __restrict__ nw1, const float* __restrict__ nb1,
    const float* __restrict__ nw2, const float* __restrict__ nb2,
    const float* __restrict__ nwo, const float* __restrict__ nbo,
    const float* __restrict__ ew0, const float* __restrict__ eb0)
{
    __shared__ float sy[4 * 96], sh0[4 * 128], sh1[4 * 64], sh2[4 * 32], sNF[4 * 64];
    const int t = threadIdx.x;
    const int nb4 = blockIdx.x * 4;

    for (int idx = t; idx < 384; idx += 256) {
        int nd = idx / 96, c = idx % 96;
        sy[idx] = (c < 64) ? g_NF[(nb4 + nd) * 64 + c]
                           : g_AGG[(nb4 + nd) * 32 + (c - 64)];
    }
    __syncthreads();
    if (t < 128) g_AGG[blockIdx.x * 128 + t] = 0.f;

    // layer 0: 96 -> 128
    {
        const int nd = t >> 6;
        const int o2 = (t & 63) * 2;
        float2 acc = *(const float2*)(nb0 + o2);
#pragma unroll 8
        for (int c = 0; c < 96; c++) {
            float v = sy[nd * 96 + c];
            float2 wv = __ldg((const float2*)(nw0 + c * 128 + o2));
            acc.x = fmaf(v, wv.x, acc.x);
            acc.y = fmaf(v, wv.y, acc.y);
        }
        sh0[nd * 128 + o2]     = fmaxf(acc.x, 0.f);
        sh0[nd * 128 + o2 + 1] = fmaxf(acc.y, 0.f);
    }
    __syncthreads();
    // layer 1: 128 -> 64
    {
        const int nd = t >> 6;
        const int o = t & 63;
        float acc = __ldg(nb1 + o);
#pragma unroll 8
        for (int c = 0; c < 128; c++)
            acc = fmaf(sh0[nd * 128 + c], __ldg(nw1 + c * 64 + o), acc);
        sh1[nd * 64 + o] = fmaxf(acc, 0.f);
    }
    __syncthreads();
    // layer 2: 64 -> 32
    if (t < 128) {
        const int nd = t >> 5;
        const int o = t & 31;
        float acc = __ldg(nb2 + o);
#pragma unroll 8
        for (int c = 0; c < 64; c++)
            acc = fmaf(sh1[nd * 64 + c], __ldg(nw2 + c * 32 + o), acc);
        sh2[nd * 32 + o] = fmaxf(acc, 0.f);
    }
    __syncthreads();
    // output: 32 -> 64, residual
    {
        const int nd = t >> 6;
        const int o = t & 63;
        float acc = __ldg(nbo + o);
#pragma unroll 8
        for (int c = 0; c < 32; c++)
            acc = fmaf(sh2[nd * 32 + c], __ldg(nwo + c * 64 + o), acc);
        float y = sy[nd * 96 + o] + acc;
        g_NF[(nb4 + nd) * 64 + o] = y;
        sNF[nd * 64 + o] = y;
    }
    __syncthreads();
    // fused projection: A = nf@ew0[0:64], B = nf@ew0[64:128]+eb0
    {
        const int nd = t >> 6;
        const int k2 = (t & 63) * 2;
        float2 a = make_float2(0.f, 0.f);
        float2 b = make_float2(0.f, 0.f);
#pragma unroll 8
        for (int c = 0; c < 64; c++) {
            float v = sNF[nd * 64 + c];
            float2 wa = __ldg((const float2*)(ew0 + c * 128 + k2));
            float2 wb = __ldg((const float2*)(ew0 + (64 + c) * 128 + k2));
            a.x = fmaf(v, wa.x, a.x); a.y = fmaf(v, wa.y, a.y);
            b.x = fmaf(v, wb.x, b.x); b.y = fmaf(v, wb.y, b.y);
        }
        float2 e = __ldg((const float2*)(eb0 + k2));
        b.x += e.x; b.y += e.y;
        const int node = nb4 + nd;
        *(float2*)(g_A + node * 128 + k2) = a;
        *(float2*)(g_B + node * 128 + k2) = b;
    }
}

// ---------------------------------------------------------------------------
__global__ void k_read(const float* __restrict__ rw, const float* __restrict__ rb,
                       float* __restrict__ out)
{
    int jn = blockIdx.x * blockDim.x + threadIdx.x;
    if (jn >= NN) return;
    float a0 = rb[0], a1 = rb[1], a2 = rb[2];
#pragma unroll
    for (int c = 0; c < 64; c++) {
        float v = g_NF[jn * FD + c];
        a0 = fmaf(v, rw[c * 3 + 0], a0);
        a1 = fmaf(v, rw[c * 3 + 1], a1);
        a2 = fmaf(v, rw[c * 3 + 2], a2);
    }
    out[jn * 3 + 0] = a0;
    out[jn * 3 + 1] = a1;
    out[jn * 3 + 2] = a2;
}

// ---------------------------------------------------------------------------
extern "C" void kernel_launch(void* const* d_in, const int* in_sizes, int n_in,
                              void* d_out, int out_size)
{
    const float* states = (const float*)d_in[0];
    const float* obj    = (const float*)d_in[1];
    const float* ew0 = (const float*)d_in[2];
    const float* eb0 = (const float*)d_in[3];
    const float* ew1 = (const float*)d_in[4];
    const float* eb1 = (const float*)d_in[5];
    const float* ew2 = (const float*)d_in[6];
    const float* eb2 = (const float*)d_in[7];
    const float* nw0 = (const float*)d_in[8];
    const float* nb0 = (const float*)d_in[9];
    const float* nw1 = (const float*)d_in[10];
    const float* nb1 = (const float*)d_in[11];
    const float* nw2 = (const float*)d_in[12];
    const float* nb2 = (const float*)d_in[13];
    const float* nwo = (const float*)d_in[14];
    const float* nbo = (const float*)d_in[15];
    const float* rw  = (const float*)d_in[16];
    const float* rb  = (const float*)d_in[17];
    float* out = (float*)d_out;

    cudaFuncSetAttribute(k_edge, cudaFuncAttributeMaxDynamicSharedMemorySize,
                         E_SMEMW * (int)sizeof(uint32_t));
    cudaFuncSetAttribute(k_proj, cudaFuncAttributeMaxDynamicSharedMemorySize,
                         PROJ_SMEM * (int)sizeof(float));

    // launch order keeps the 2nd k_edge at index 5 (ncu -s 5 -c 1 capture slot)
    k_init_nf<<<128, 256>>>(states, obj);
    k_init_dist<<<NN, 256>>>(states);
    k_proj<<<64, 256, PROJ_SMEM * (int)sizeof(float)>>>(ew0, eb0);
    for (int it = 0; it < 3; it++) {
        k_edge<<<EGRID, 256, E_SMEMW * (int)sizeof(uint32_t)>>>(ew0, ew1, eb1, ew2, eb2);
        k_node<<<128, 256>>>(nw0, nb0, nw1, nb1, nw2, nb2, nwo, nbo, ew0, eb0);
    }
    k_read<<<4, 128>>>(rw, rb, out);
}

// round 10
// speedup vs baseline: 1.8416x; 1.5954x over previous
#include <cuda_runtime.h>
#include <cuda_fp16.h>
#include <math.h>
#include <stdint.h>

// ---------------------------------------------------------------------------
// FormationOptimizer: fully-connected GNN, N=512, 3 message-passing rounds.
// Edge layer0 factorized: A[i] + B[j] + dist*wd (fp32). Edge MLP GEMMs on
// tensor cores via mma.sync.m16n8k16 fp16 with ldmatrix.x4 fragment loads,
// fp32 register accumulators; bias/relu/mask/reduce in-register.
// ---------------------------------------------------------------------------

#define NN 512
#define FD 64
#define H0D 128

__device__ float g_NF[NN * FD];
__device__ float g_DIST[NN * NN];
__device__ float g_A[NN * H0D];      // nf @ ew0[0:64]        [node][k]
__device__ float g_B[NN * H0D];      // nf @ ew0[64:128]+eb0  [node][k]
__device__ float g_AGG[NN * 32];

__device__ __forceinline__ uint32_t pack_h2(float lo, float hi) {
    __half2 h = __floats2half2_rn(lo, hi);
    return *(uint32_t*)&h;
}
__device__ __forceinline__ void mma16(float* c, const uint32_t* a, const uint32_t* b) {
    asm volatile(
        "mma.sync.aligned.m16n8k16.row.col.f32.f16.f16.f32 "
        "{%0,%1,%2,%3}, {%4,%5,%6,%7}, {%8,%9}, {%0,%1,%2,%3};"
        : "+f"(c[0]), "+f"(c[1]), "+f"(c[2]), "+f"(c[3])
        : "r"(a[0]), "r"(a[1]), "r"(a[2]), "r"(a[3]), "r"(b[0]), "r"(b[1]));
}
__device__ __forceinline__ void ldsm4(uint32_t* r, uint32_t saddr) {
    asm volatile(
        "ldmatrix.sync.aligned.m8n8.x4.shared.b16 {%0,%1,%2,%3}, [%4];"
        : "=r"(r[0]), "=r"(r[1]), "=r"(r[2]), "=r"(r[3]) : "r"(saddr));
}

// ---------------------------------------------------------------------------
__global__ void k_init_nf(const float* __restrict__ states,
                          const float* __restrict__ obj) {
    int idx = blockIdx.x * 256 + threadIdx.x;
    int i = idx >> 6, c = idx & 63;
    g_NF[idx] = (c < 6) ? states[i * 6 + c] : obj[c - 6];
}

__global__ void k_init_dist(const float* __restrict__ states) {
    int i = blockIdx.x, t = threadIdx.x;
    float px = states[i * 6 + 0], py = states[i * 6 + 1], pz = states[i * 6 + 2];
    for (int j = t; j < NN; j += blockDim.x) {
        float dx = states[j * 6 + 0] - px;
        float dy = states[j * 6 + 1] - py;
        float dz = states[j * 6 + 2] - pz;
        g_DIST[i * NN + j] = sqrtf(dx * dx + dy * dy + dz * dz);
    }
}

// ---------------------------------------------------------------------------
// k_proj: A/B for iteration 0, zero g_AGG.
// ---------------------------------------------------------------------------
#define PROJ_SMEM (16384 + 512)
__global__ void __launch_bounds__(256) k_proj(const float* __restrict__ ew0,
                                              const float* __restrict__ eb0) {
    extern __shared__ float sm[];
    float* sE = sm;
    float* snf = sm + 16384;
    const int t = threadIdx.x;
    const int nb8 = blockIdx.x * 8;

    for (int q = 0; q < 16; q++)
        *(float4*)(sE + q * 1024 + t * 4) = *(const float4*)(ew0 + q * 1024 + t * 4);
    for (int q = 0; q < 2; q++)
        snf[q * 256 + t] = g_NF[nb8 * 64 + q * 256 + t];
    g_AGG[blockIdx.x * 256 + t] = 0.f;
    __syncthreads();

    const int nd = t >> 5;
    const int k4 = (t & 31) * 4;
    float4 a = make_float4(0.f, 0.f, 0.f, 0.f);
    float4 b = make_float4(0.f, 0.f, 0.f, 0.f);
#pragma unroll 4
    for (int c = 0; c < 64; c++) {
        float v = snf[nd * 64 + c];
        float4 wa = *(const float4*)(sE + c * 128 + k4);
        float4 wb = *(const float4*)(sE + (64 + c) * 128 + k4);
        a.x = fmaf(v, wa.x, a.x); a.y = fmaf(v, wa.y, a.y);
        a.z = fmaf(v, wa.z, a.z); a.w = fmaf(v, wa.w, a.w);
        b.x = fmaf(v, wb.x, b.x); b.y = fmaf(v, wb.y, b.y);
        b.z = fmaf(v, wb.z, b.z); b.w = fmaf(v, wb.w, b.w);
    }
    float4 e = *(const float4*)(eb0 + k4);
    b.x += e.x; b.y += e.y; b.z += e.z; b.w += e.w;
    *(float4*)(g_A + (nb8 + nd) * 128 + k4) = a;
    *(float4*)(g_B + (nb8 + nd) * 128 + k4) = b;
}

// ---------------------------------------------------------------------------
// k_edge: persistent mma fp16 + ldmatrix. grid=296 (2 CTAs/SM), 256 threads.
// Items: 2048 = 512 receivers x 4 sender-tiles (128 senders each).
// smem words: W1t[64][68] | W2t[32][36] | H0[128][68] | H1[128][36]
// ---------------------------------------------------------------------------
#define S_W1T 0
#define S_W2T 4352
#define S_H0  5504
#define S_H1  14208
#define E_SMEMW 18816    // words -> 75264 bytes

#define NITEM 2048
#define EGRID 296

// H0[e][k] = relu(A[i][k] + B[j][k] + d*wd[k]); warp w builds 16 edge-rows.
__device__ __forceinline__ void compute_H0(uint32_t* __restrict__ sH0w,
                                           int item, int w, int lane,
                                           const float4 wv,
                                           const float4* __restrict__ Bj)
{
    const int j = item >> 2;
    const int ibase = (item & 3) * 128;
    const int eb = ibase + w * 16;
    float dl = 0.f;
    if (lane < 16) dl = __ldg(g_DIST + j * NN + eb + lane);
    const float4 bv = __ldg(Bj + lane);   // B[j][4*lane .. +3]
    uint32_t* dst = sH0w + (w * 16) * 68 + 2 * lane;
#pragma unroll
    for (int e = 0; e < 16; e++) {
        float d = __shfl_sync(0xffffffffu, dl, e);
        float4 av = __ldg((const float4*)(g_A + (eb + e) * H0D) + lane);
        float h0 = fmaxf(fmaf(d, wv.x, av.x + bv.x), 0.f);
        float h1 = fmaxf(fmaf(d, wv.y, av.y + bv.y), 0.f);
        float h2 = fmaxf(fmaf(d, wv.z, av.z + bv.z), 0.f);
        float h3 = fmaxf(fmaf(d, wv.w, av.w + bv.w), 0.f);
        uint2 u;
        u.x = pack_h2(h0, h1);
        u.y = pack_h2(h2, h3);
        *(uint2*)(dst + e * 68) = u;
    }
}

__global__ void __launch_bounds__(256, 2) k_edge(
    const float* __restrict__ ew0, const float* __restrict__ ew1,
    const float* __restrict__ eb1, const float* __restrict__ ew2,
    const float* __restrict__ eb2)
{
    extern __shared__ uint32_t smw[];
    uint32_t* sW1tw = smw + S_W1T;
    uint32_t* sW2tw = smw + S_W2T;
    uint32_t* sH0w  = smw + S_H0;
    uint32_t* sH1w  = smw + S_H1;
    const uint32_t sb = (uint32_t)__cvta_generic_to_shared(smw);

    const int t = threadIdx.x;
    const int lane = t & 31;
    const int w = t >> 5;
    const int ar = lane >> 2;
    const int ac = lane & 3;

    // ---- stage weights (transposed, fp16 pairs) once per CTA ----
    for (int idx = t; idx < 4096; idx += 256) {
        int n = idx >> 6, wk = idx & 63;
        sW1tw[n * 68 + wk] = pack_h2(__ldg(ew1 + (2 * wk) * 64 + n),
                                     __ldg(ew1 + (2 * wk + 1) * 64 + n));
    }
    for (int idx = t; idx < 1024; idx += 256) {
        int m = idx >> 5, wk = idx & 31;
        sW2tw[m * 36 + wk] = pack_h2(__ldg(ew2 + (2 * wk) * 32 + m),
                                     __ldg(ew2 + (2 * wk + 1) * 32 + m));
    }

    // ldmatrix per-lane offsets (word units)
    const int lrowA = ((lane >> 3) & 1) * 8 + (lane & 7);
    const int lcolA = (lane >> 4) * 4;
    const int lrowB = ((lane >> 4) & 1) * 8 + (lane & 7);
    const int lcolB = ((lane >> 3) & 1) * 4;

    // GEMM1 warp tile: edges [mw, mw+32), cols [nw, nw+32)
    const int mw = (w >> 1) * 32;
    const int nw = (w & 1) * 32;
    float e1b[4][2];
#pragma unroll
    for (int ni = 0; ni < 4; ni++) {
        e1b[ni][0] = __ldg(eb1 + nw + ni * 8 + 2 * ac);
        e1b[ni][1] = __ldg(eb1 + nw + ni * 8 + 2 * ac + 1);
    }
    // GEMM2 warp tile: edges [mw2, mw2+32), cols [mb2, mb2+16)
    const int mw2 = (w & 3) * 32;
    const int mb2 = (w >> 2) * 16;
    float e2b[2][2];
#pragma unroll
    for (int ni = 0; ni < 2; ni++) {
        e2b[ni][0] = __ldg(eb2 + mb2 + ni * 8 + 2 * ac);
        e2b[ni][1] = __ldg(eb2 + mb2 + ni * 8 + 2 * ac + 1);
    }

    // constants for H0 build
    const float4 wv = __ldg((const float4*)(ew0 + 128 * H0D) + lane);

    // ldmatrix base addresses (bytes)
    const uint32_t aH0_0 = sb + (S_H0 + (mw + lrowA) * 68 + lcolA) * 4;
    const uint32_t aH0_1 = aH0_0 + 16 * 68 * 4;
    const uint32_t aW1_0 = sb + (S_W1T + (nw + lrowB) * 68 + lcolB) * 4;
    const uint32_t aW1_1 = aW1_0 + 16 * 68 * 4;
    const uint32_t aH1_0 = sb + (S_H1 + (mw2 + lrowA) * 36 + lcolA) * 4;
    const uint32_t aH1_1 = aH1_0 + 16 * 36 * 4;
    const uint32_t aW2   = sb + (S_W2T + (mb2 + lrowB) * 36 + lcolB) * 4;

    int item = blockIdx.x;
    if (item < NITEM)
        compute_H0(sH0w, item, w, lane,
                   wv, (const float4*)(g_B + (item >> 2) * H0D));
    __syncthreads();

    while (item < NITEM) {
        const int j = item >> 2;
        const int ibase = (item & 3) * 128;

        // ================ GEMM1: H1 = relu(H0 @ W1 + b1) ================
        {
            float acc[2][4][4];
#pragma unroll
            for (int mi = 0; mi < 2; mi++)
#pragma unroll
                for (int ni = 0; ni < 4; ni++) {
                    acc[mi][ni][0] = e1b[ni][0];
                    acc[mi][ni][1] = e1b[ni][1];
                    acc[mi][ni][2] = e1b[ni][0];
                    acc[mi][ni][3] = e1b[ni][1];
                }
#pragma unroll
            for (int ks = 0; ks < 8; ks++) {
                const uint32_t koff = ks * 8 * 4;     // 8 words per k-step
                uint32_t a[2][4], bb[2][4];
                ldsm4(a[0], aH0_0 + koff);
                ldsm4(a[1], aH0_1 + koff);
                ldsm4(bb[0], aW1_0 + koff);
                ldsm4(bb[1], aW1_1 + koff);
#pragma unroll
                for (int mi = 0; mi < 2; mi++)
#pragma unroll
                    for (int ni = 0; ni < 4; ni++)
                        mma16(acc[mi][ni], a[mi], &bb[ni >> 1][(ni & 1) * 2]);
            }
            // epilogue: relu -> fp16 pairs into H1
#pragma unroll
            for (int mi = 0; mi < 2; mi++) {
                const int r0 = mw + mi * 16 + ar;
#pragma unroll
                for (int ni = 0; ni < 4; ni++) {
                    const int wc = (nw >> 1) + ni * 4 + ac;
                    sH1w[r0 * 36 + wc] =
                        pack_h2(fmaxf(acc[mi][ni][0], 0.f), fmaxf(acc[mi][ni][1], 0.f));
                    sH1w[(r0 + 8) * 36 + wc] =
                        pack_h2(fmaxf(acc[mi][ni][2], 0.f), fmaxf(acc[mi][ni][3], 0.f));
                }
            }
        }
        __syncthreads();   // H1 visible; H0 free

        // ================ GEMM2 + masked reduction ================
        {
            float acc[2][2][4];
#pragma unroll
            for (int mi = 0; mi < 2; mi++)
#pragma unroll
                for (int ni = 0; ni < 2; ni++) {
                    acc[mi][ni][0] = e2b[ni][0];
                    acc[mi][ni][1] = e2b[ni][1];
                    acc[mi][ni][2] = e2b[ni][0];
                    acc[mi][ni][3] = e2b[ni][1];
                }
#pragma unroll
            for (int ks = 0; ks < 4; ks++) {
                const uint32_t koff = ks * 8 * 4;
                uint32_t a[2][4], bb[4];
                ldsm4(a[0], aH1_0 + koff);
                ldsm4(a[1], aH1_1 + koff);
                ldsm4(bb, aW2 + koff);
#pragma unroll
                for (int mi = 0; mi < 2; mi++) {
                    mma16(acc[mi][0], a[mi], &bb[0]);
                    mma16(acc[mi][1], a[mi], &bb[2]);
                }
            }
            float s[2][2] = {{0.f, 0.f}, {0.f, 0.f}};
#pragma unroll
            for (int mi = 0; mi < 2; mi++) {
                const int i0 = ibase + mw2 + mi * 16 + ar;
                const bool k0 = (i0 != j);
                const bool k1 = (i0 + 8 != j);
#pragma unroll
                for (int ni = 0; ni < 2; ni++) {
                    if (k0) {
                        s[ni][0] += fmaxf(acc[mi][ni][0], 0.f);
                        s[ni][1] += fmaxf(acc[mi][ni][1], 0.f);
                    }
                    if (k1) {
                        s[ni][0] += fmaxf(acc[mi][ni][2], 0.f);
                        s[ni][1] += fmaxf(acc[mi][ni][3], 0.f);
                    }
                }
            }
#pragma unroll
            for (int off = 4; off <= 16; off <<= 1) {
#pragma unroll
                for (int ni = 0; ni < 2; ni++) {
                    s[ni][0] += __shfl_xor_sync(0xffffffffu, s[ni][0], off);
                    s[ni][1] += __shfl_xor_sync(0xffffffffu, s[ni][1], off);
                }
            }
            if (lane < 4) {
                float* dst = g_AGG + j * 32 + mb2 + 2 * ac;
                atomicAdd(dst + 0, s[0][0]);
                atomicAdd(dst + 1, s[0][1]);
                atomicAdd(dst + 8, s[1][0]);
                atomicAdd(dst + 9, s[1][1]);
            }
        }

        // H0 for next item (H0 free since the GEMM1->GEMM2 barrier)
        const int nxt = item + EGRID;
        if (nxt < NITEM)
            compute_H0(sH0w, nxt, w, lane,
                       wv, (const float4*)(g_B + (nxt >> 2) * H0D));
        __syncthreads();   // H0(next) visible; H1 free
        item = nxt;
    }
}

// ---------------------------------------------------------------------------
// k_node: 128 CTAs x 4 nodes, 256 threads. Node MLP + residual, fused
// projection (A/B for next edge pass), zero g_AGG.
// ---------------------------------------------------------------------------
__global__ void __launch_bounds__(256) k_node(
    const float* __restrict__ nw0, const float* __restrict__ nb0,
    const float* __restrict__ nw1, const float* __restrict__ nb1,
    const float* __restrict__ nw2, const float* __restrict__ nb2,
    const float* __restrict__ nwo, const float* __restrict__ nbo,
    const float* __restrict__ ew0, const float* __restrict__ eb0)
{
    __shared__ float sy[4 * 96], sh0[4 * 128], sh1[4 * 64], sh2[4 * 32], sNF[4 * 64];
    const int t = threadIdx.x;
    const int nb4 = blockIdx.x * 4;

    for (int idx = t; idx < 384; idx += 256) {
        int nd = idx / 96, c = idx % 96;
        sy[idx] = (c < 64) ? g_NF[(nb4 + nd) * 64 + c]
                           : g_AGG[(nb4 + nd) * 32 + (c - 64)];
    }
    __syncthreads();
    if (t < 128) g_AGG[blockIdx.x * 128 + t] = 0.f;

    // layer 0: 96 -> 128
    {
        const int nd = t >> 6;
        const int o2 = (t & 63) * 2;
        float2 acc = *(const float2*)(nb0 + o2);
#pragma unroll 8
        for (int c = 0; c < 96; c++) {
            float v = sy[nd * 96 + c];
            float2 wv = __ldg((const float2*)(nw0 + c * 128 + o2));
            acc.x = fmaf(v, wv.x, acc.x);
            acc.y = fmaf(v, wv.y, acc.y);
        }
        sh0[nd * 128 + o2]     = fmaxf(acc.x, 0.f);
        sh0[nd * 128 + o2 + 1] = fmaxf(acc.y, 0.f);
    }
    __syncthreads();
    // layer 1: 128 -> 64
    {
        const int nd = t >> 6;
        const int o = t & 63;
        float acc = __ldg(nb1 + o);
#pragma unroll 8
        for (int c = 0; c < 128; c++)
            acc = fmaf(sh0[nd * 128 + c], __ldg(nw1 + c * 64 + o), acc);
        sh1[nd * 64 + o] = fmaxf(acc, 0.f);
    }
    __syncthreads();
    // layer 2: 64 -> 32
    if (t < 128) {
        const int nd = t >> 5;
        const int o = t & 31;
        float acc = __ldg(nb2 + o);
#pragma unroll 8
        for (int c = 0; c < 64; c++)
            acc = fmaf(sh1[nd * 64 + c], __ldg(nw2 + c * 32 + o), acc);
        sh2[nd * 32 + o] = fmaxf(acc, 0.f);
    }
    __syncthreads();
    // output: 32 -> 64, residual
    {
        const int nd = t >> 6;
        const int o = t & 63;
        float acc = __ldg(nbo + o);
#pragma unroll 8
        for (int c = 0; c < 32; c++)
            acc = fmaf(sh2[nd * 32 + c], __ldg(nwo + c * 64 + o), acc);
        float y = sy[nd * 96 + o] + acc;
        g_NF[(nb4 + nd) * 64 + o] = y;
        sNF[nd * 64 + o] = y;
    }
    __syncthreads();
    // fused projection: A = nf@ew0[0:64], B = nf@ew0[64:128]+eb0
    {
        const int nd = t >> 6;
        const int k2 = (t & 63) * 2;
        float2 a = make_float2(0.f, 0.f);
        float2 b = make_float2(0.f, 0.f);
#pragma unroll 8
        for (int c = 0; c < 64; c++) {
            float v = sNF[nd * 64 + c];
            float2 wa = __ldg((const float2*)(ew0 + c * 128 + k2));
            float2 wb = __ldg((const float2*)(ew0 + (64 + c) * 128 + k2));
            a.x = fmaf(v, wa.x, a.x); a.y = fmaf(v, wa.y, a.y);
            b.x = fmaf(v, wb.x, b.x); b.y = fmaf(v, wb.y, b.y);
        }
        float2 e = __ldg((const float2*)(eb0 + k2));
        b.x += e.x; b.y += e.y;
        const int node = nb4 + nd;
        *(float2*)(g_A + node * 128 + k2) = a;
        *(float2*)(g_B + node * 128 + k2) = b;
    }
}

// ---------------------------------------------------------------------------
__global__ void k_read(const float* __restrict__ rw, const float* __restrict__ rb,
                       float* __restrict__ out)
{
    int jn = blockIdx.x * blockDim.x + threadIdx.x;
    if (jn >= NN) return;
    float a0 = rb[0], a1 = rb[1], a2 = rb[2];
#pragma unroll
    for (int c = 0; c < 64; c++) {
        float v = g_NF[jn * FD + c];
        a0 = fmaf(v, rw[c * 3 + 0], a0);
        a1 = fmaf(v, rw[c * 3 + 1], a1);
        a2 = fmaf(v, rw[c * 3 + 2], a2);
    }
    out[jn * 3 + 0] = a0;
    out[jn * 3 + 1] = a1;
    out[jn * 3 + 2] = a2;
}

// ---------------------------------------------------------------------------
extern "C" void kernel_launch(void* const* d_in, const int* in_sizes, int n_in,
                              void* d_out, int out_size)
{
    const float* states = (const float*)d_in[0];
    const float* obj    = (const float*)d_in[1];
    const float* ew0 = (const float*)d_in[2];
    const float* eb0 = (const float*)d_in[3];
    const float* ew1 = (const float*)d_in[4];
    const float* eb1 = (const float*)d_in[5];
    const float* ew2 = (const float*)d_in[6];
    const float* eb2 = (const float*)d_in[7];
    const float* nw0 = (const float*)d_in[8];
    const float* nb0 = (const float*)d_in[9];
    const float* nw1 = (const float*)d_in[10];
    const float* nb1 = (const float*)d_in[11];
    const float* nw2 = (const float*)d_in[12];
    const float* nb2 = (const float*)d_in[13];
    const float* nwo = (const float*)d_in[14];
    const float* nbo = (const float*)d_in[15];
    const float* rw  = (const float*)d_in[16];
    const float* rb  = (const float*)d_in[17];
    float* out = (float*)d_out;

    cudaFuncSetAttribute(k_edge, cudaFuncAttributeMaxDynamicSharedMemorySize,
                         E_SMEMW * (int)sizeof(uint32_t));
    cudaFuncSetAttribute(k_proj, cudaFuncAttributeMaxDynamicSharedMemorySize,
                         PROJ_SMEM * (int)sizeof(float));

    // launch order keeps the 2nd k_edge at index 5 (ncu -s 5 -c 1 capture slot)
    k_init_nf<<<128, 256>>>(states, obj);
    k_init_dist<<<NN, 256>>>(states);
    k_proj<<<64, 256, PROJ_SMEM * (int)sizeof(float)>>>(ew0, eb0);
    for (int it = 0; it < 3; it++) {
        k_edge<<<EGRID, 256, E_SMEMW * (int)sizeof(uint32_t)>>>(ew0, ew1, eb1, ew2, eb2);
        k_node<<<128, 256>>>(nw0, nb0, nw1, nb1, nw2, nb2, nwo, nbo, ew0, eb0);
    }
    k_read<<<4, 128>>>(rw, rb, out);
}

// round 11
// speedup vs baseline: 1.9789x; 1.0746x over previous
#include <cuda_runtime.h>
#include <cuda_fp16.h>
#include <math.h>
#include <stdint.h>

// ---------------------------------------------------------------------------
// FormationOptimizer: fully-connected GNN, N=512, 3 message-passing rounds.
// Edge layer0 factorized: A[i] + B[j] + dist*wd (fp32). Edge MLP GEMMs on
// tensor cores via mma.sync.m16n8k16 fp16 with ldmatrix fragment loads.
// W1 fragments live in registers across the whole persistent loop.
// ---------------------------------------------------------------------------

#define NN 512
#define FD 64
#define H0D 128

__device__ float g_NF[NN * FD];
__device__ float g_DIST[NN * NN];
__device__ float g_A[NN * H0D];      // nf @ ew0[0:64]        [node][k]
__device__ float g_B[NN * H0D];      // nf @ ew0[64:128]+eb0  [node][k]
__device__ float g_AGG[NN * 32];

__device__ __forceinline__ uint32_t pack_h2(float lo, float hi) {
    __half2 h = __floats2half2_rn(lo, hi);
    return *(uint32_t*)&h;
}
__device__ __forceinline__ void mma16(float* c, const uint32_t* a, const uint32_t* b) {
    asm volatile(
        "mma.sync.aligned.m16n8k16.row.col.f32.f16.f16.f32 "
        "{%0,%1,%2,%3}, {%4,%5,%6,%7}, {%8,%9}, {%0,%1,%2,%3};"
        : "+f"(c[0]), "+f"(c[1]), "+f"(c[2]), "+f"(c[3])
        : "r"(a[0]), "r"(a[1]), "r"(a[2]), "r"(a[3]), "r"(b[0]), "r"(b[1]));
}
__device__ __forceinline__ void ldsm4(uint32_t* r, uint32_t saddr) {
    asm volatile(
        "ldmatrix.sync.aligned.m8n8.x4.shared.b16 {%0,%1,%2,%3}, [%4];"
        : "=r"(r[0]), "=r"(r[1]), "=r"(r[2]), "=r"(r[3]) : "r"(saddr));
}

// ---------------------------------------------------------------------------
__global__ void k_init_nf(const float* __restrict__ states,
                          const float* __restrict__ obj) {
    int idx = blockIdx.x * 256 + threadIdx.x;
    int i = idx >> 6, c = idx & 63;
    g_NF[idx] = (c < 6) ? states[i * 6 + c] : obj[c - 6];
}

__global__ void k_init_dist(const float* __restrict__ states) {
    int i = blockIdx.x, t = threadIdx.x;
    float px = states[i * 6 + 0], py = states[i * 6 + 1], pz = states[i * 6 + 2];
    for (int j = t; j < NN; j += blockDim.x) {
        float dx = states[j * 6 + 0] - px;
        float dy = states[j * 6 + 1] - py;
        float dz = states[j * 6 + 2] - pz;
        g_DIST[i * NN + j] = sqrtf(dx * dx + dy * dy + dz * dz);
    }
}

// ---------------------------------------------------------------------------
// k_proj: A/B for iteration 0, zero g_AGG.
// ---------------------------------------------------------------------------
#define PROJ_SMEM (16384 + 512)
__global__ void __launch_bounds__(256) k_proj(const float* __restrict__ ew0,
                                              const float* __restrict__ eb0) {
    extern __shared__ float sm[];
    float* sE = sm;
    float* snf = sm + 16384;
    const int t = threadIdx.x;
    const int nb8 = blockIdx.x * 8;

    for (int q = 0; q < 16; q++)
        *(float4*)(sE + q * 1024 + t * 4) = *(const float4*)(ew0 + q * 1024 + t * 4);
    for (int q = 0; q < 2; q++)
        snf[q * 256 + t] = g_NF[nb8 * 64 + q * 256 + t];
    g_AGG[blockIdx.x * 256 + t] = 0.f;
    __syncthreads();

    const int nd = t >> 5;
    const int k4 = (t & 31) * 4;
    float4 a = make_float4(0.f, 0.f, 0.f, 0.f);
    float4 b = make_float4(0.f, 0.f, 0.f, 0.f);
#pragma unroll 4
    for (int c = 0; c < 64; c++) {
        float v = snf[nd * 64 + c];
        float4 wa = *(const float4*)(sE + c * 128 + k4);
        float4 wb = *(const float4*)(sE + (64 + c) * 128 + k4);
        a.x = fmaf(v, wa.x, a.x); a.y = fmaf(v, wa.y, a.y);
        a.z = fmaf(v, wa.z, a.z); a.w = fmaf(v, wa.w, a.w);
        b.x = fmaf(v, wb.x, b.x); b.y = fmaf(v, wb.y, b.y);
        b.z = fmaf(v, wb.z, b.z); b.w = fmaf(v, wb.w, b.w);
    }
    float4 e = *(const float4*)(eb0 + k4);
    b.x += e.x; b.y += e.y; b.z += e.z; b.w += e.w;
    *(float4*)(g_A + (nb8 + nd) * 128 + k4) = a;
    *(float4*)(g_B + (nb8 + nd) * 128 + k4) = b;
}

// ---------------------------------------------------------------------------
// k_edge: persistent mma fp16 + ldmatrix. grid=296 (2 CTAs/SM), 256 threads.
// Items: 2048 = 512 receivers x 4 sender-tiles (128 senders each).
// smem words: W1t[64][68] (init only) | W2t[32][36] | H0[128][68] | H1[128][36]
// ---------------------------------------------------------------------------
#define S_W1T 0
#define S_W2T 4352
#define S_H0  5504
#define S_H1  14208
#define E_SMEMW 18816    // words -> 75264 bytes

#define NITEM 2048
#define EGRID 296

// H0[e][k] = relu(A[i][k] + B[j][k] + d*wd[k]); warp w builds 16 edge-rows.
__device__ __forceinline__ void compute_H0(uint32_t* __restrict__ sH0w,
                                           int item, int w, int lane,
                                           const float4 wv,
                                           const float4* __restrict__ Bj)
{
    const int j = item >> 2;
    const int ibase = (item & 3) * 128;
    const int eb = ibase + w * 16;
    float dl = 0.f;
    if (lane < 16) dl = __ldg(g_DIST + j * NN + eb + lane);
    const float4 bv = __ldg(Bj + lane);   // B[j][4*lane .. +3]
    uint32_t* dst = sH0w + (w * 16) * 68 + 2 * lane;
#pragma unroll
    for (int e = 0; e < 16; e++) {
        float d = __shfl_sync(0xffffffffu, dl, e);
        float4 av = __ldg((const float4*)(g_A + (eb + e) * H0D) + lane);
        float h0 = fmaxf(fmaf(d, wv.x, av.x + bv.x), 0.f);
        float h1 = fmaxf(fmaf(d, wv.y, av.y + bv.y), 0.f);
        float h2 = fmaxf(fmaf(d, wv.z, av.z + bv.z), 0.f);
        float h3 = fmaxf(fmaf(d, wv.w, av.w + bv.w), 0.f);
        uint2 u;
        u.x = pack_h2(h0, h1);
        u.y = pack_h2(h2, h3);
        *(uint2*)(dst + e * 68) = u;
    }
}

__global__ void __launch_bounds__(256, 2) k_edge(
    const float* __restrict__ ew0, const float* __restrict__ ew1,
    const float* __restrict__ eb1, const float* __restrict__ ew2,
    const float* __restrict__ eb2)
{
    extern __shared__ uint32_t smw[];
    uint32_t* sW1tw = smw + S_W1T;
    uint32_t* sW2tw = smw + S_W2T;
    uint32_t* sH0w  = smw + S_H0;
    uint32_t* sH1w  = smw + S_H1;
    const uint32_t sb = (uint32_t)__cvta_generic_to_shared(smw);

    const int t = threadIdx.x;
    const int lane = t & 31;
    const int w = t >> 5;
    const int ar = lane >> 2;
    const int ac = lane & 3;

    // ---- stage weights (transposed, fp16 pairs) once per CTA ----
    for (int idx = t; idx < 4096; idx += 256) {
        int n = idx >> 6, wk = idx & 63;
        sW1tw[n * 68 + wk] = pack_h2(__ldg(ew1 + (2 * wk) * 64 + n),
                                     __ldg(ew1 + (2 * wk + 1) * 64 + n));
    }
    for (int idx = t; idx < 1024; idx += 256) {
        int m = idx >> 5, wk = idx & 31;
        sW2tw[m * 36 + wk] = pack_h2(__ldg(ew2 + (2 * wk) * 32 + m),
                                     __ldg(ew2 + (2 * wk + 1) * 32 + m));
    }

    // ldmatrix per-lane offsets (word units)
    const int lrowA = ((lane >> 3) & 1) * 8 + (lane & 7);
    const int lcolA = (lane >> 4) * 4;
    const int lrowB = ((lane >> 4) & 1) * 8 + (lane & 7);
    const int lcolB = ((lane >> 3) & 1) * 4;

    // GEMM1 warp tile: edges [mw, mw+32), cols [nw, nw+32)
    const int mw = (w >> 1) * 32;
    const int nw = (w & 1) * 32;
    float e1b[4][2];
#pragma unroll
    for (int ni = 0; ni < 4; ni++) {
        e1b[ni][0] = __ldg(eb1 + nw + ni * 8 + 2 * ac);
        e1b[ni][1] = __ldg(eb1 + nw + ni * 8 + 2 * ac + 1);
    }
    // GEMM2 warp tile: edges [mw2, mw2+32), cols [mb2, mb2+16)
    const int mw2 = (w & 3) * 32;
    const int mb2 = (w >> 2) * 16;
    float e2b[2][2];
#pragma unroll
    for (int ni = 0; ni < 2; ni++) {
        e2b[ni][0] = __ldg(eb2 + mb2 + ni * 8 + 2 * ac);
        e2b[ni][1] = __ldg(eb2 + mb2 + ni * 8 + 2 * ac + 1);
    }

    // constants for H0 build
    const float4 wv = __ldg((const float4*)(ew0 + 128 * H0D) + lane);

    // ldmatrix base addresses (bytes)
    const uint32_t aH0_0 = sb + (S_H0 + (mw + lrowA) * 68 + lcolA) * 4;
    const uint32_t aH0_1 = aH0_0 + 16 * 68 * 4;
    const uint32_t aW1_0 = sb + (S_W1T + (nw + lrowB) * 68 + lcolB) * 4;
    const uint32_t aW1_1 = aW1_0 + 16 * 68 * 4;
    const uint32_t aH1_0 = sb + (S_H1 + (mw2 + lrowA) * 36 + lcolA) * 4;
    const uint32_t aH1_1 = aH1_0 + 16 * 36 * 4;
    const uint32_t aW2   = sb + (S_W2T + (mb2 + lrowB) * 36 + lcolB) * 4;

    __syncthreads();   // W1t/W2t staged

    // ---- hold ALL W1 fragments in registers for the whole kernel ----
    uint32_t w1f[8][8];
#pragma unroll
    for (int ks = 0; ks < 8; ks++) {
        ldsm4(&w1f[ks][0], aW1_0 + ks * 32);
        ldsm4(&w1f[ks][4], aW1_1 + ks * 32);
    }

    int item = blockIdx.x;
    if (item < NITEM)
        compute_H0(sH0w, item, w, lane,
                   wv, (const float4*)(g_B + (item >> 2) * H0D));
    __syncthreads();

    while (item < NITEM) {
        const int j = item >> 2;
        const int ibase = (item & 3) * 128;

        // ================ GEMM1: H1 = relu(H0 @ W1 + b1) ================
        {
            float acc[2][4][4];
#pragma unroll
            for (int mi = 0; mi < 2; mi++)
#pragma unroll
                for (int ni = 0; ni < 4; ni++) {
                    acc[mi][ni][0] = e1b[ni][0];
                    acc[mi][ni][1] = e1b[ni][1];
                    acc[mi][ni][2] = e1b[ni][0];
                    acc[mi][ni][3] = e1b[ni][1];
                }
#pragma unroll
            for (int ks = 0; ks < 8; ks++) {
                const uint32_t koff = ks * 8 * 4;     // 8 words per k-step
                uint32_t a[2][4];
                ldsm4(a[0], aH0_0 + koff);
                ldsm4(a[1], aH0_1 + koff);
#pragma unroll
                for (int mi = 0; mi < 2; mi++)
#pragma unroll
                    for (int ni = 0; ni < 4; ni++)
                        mma16(acc[mi][ni], a[mi],
                              &w1f[ks][(ni >> 1) * 4 + (ni & 1) * 2]);
            }
            // epilogue: relu -> fp16 pairs into H1
#pragma unroll
            for (int mi = 0; mi < 2; mi++) {
                const int r0 = mw + mi * 16 + ar;
#pragma unroll
                for (int ni = 0; ni < 4; ni++) {
                    const int wc = (nw >> 1) + ni * 4 + ac;
                    sH1w[r0 * 36 + wc] =
                        pack_h2(fmaxf(acc[mi][ni][0], 0.f), fmaxf(acc[mi][ni][1], 0.f));
                    sH1w[(r0 + 8) * 36 + wc] =
                        pack_h2(fmaxf(acc[mi][ni][2], 0.f), fmaxf(acc[mi][ni][3], 0.f));
                }
            }
        }
        __syncthreads();   // H1 visible; H0 free

        // ================ GEMM2 + masked reduction ================
        {
            float acc[2][2][4];
#pragma unroll
            for (int mi = 0; mi < 2; mi++)
#pragma unroll
                for (int ni = 0; ni < 2; ni++) {
                    acc[mi][ni][0] = e2b[ni][0];
                    acc[mi][ni][1] = e2b[ni][1];
                    acc[mi][ni][2] = e2b[ni][0];
                    acc[mi][ni][3] = e2b[ni][1];
                }
#pragma unroll
            for (int ks = 0; ks < 4; ks++) {
                const uint32_t koff = ks * 8 * 4;
                uint32_t a[2][4], bb[4];
                ldsm4(a[0], aH1_0 + koff);
                ldsm4(a[1], aH1_1 + koff);
                ldsm4(bb, aW2 + koff);
#pragma unroll
                for (int mi = 0; mi < 2; mi++) {
                    mma16(acc[mi][0], a[mi], &bb[0]);
                    mma16(acc[mi][1], a[mi], &bb[2]);
                }
            }
            float s[2][2] = {{0.f, 0.f}, {0.f, 0.f}};
#pragma unroll
            for (int mi = 0; mi < 2; mi++) {
                const int i0 = ibase + mw2 + mi * 16 + ar;
                const bool k0 = (i0 != j);
                const bool k1 = (i0 + 8 != j);
#pragma unroll
                for (int ni = 0; ni < 2; ni++) {
                    if (k0) {
                        s[ni][0] += fmaxf(acc[mi][ni][0], 0.f);
                        s[ni][1] += fmaxf(acc[mi][ni][1], 0.f);
                    }
                    if (k1) {
                        s[ni][0] += fmaxf(acc[mi][ni][2], 0.f);
                        s[ni][1] += fmaxf(acc[mi][ni][3], 0.f);
                    }
                }
            }
#pragma unroll
            for (int off = 4; off <= 16; off <<= 1) {
#pragma unroll
                for (int ni = 0; ni < 2; ni++) {
                    s[ni][0] += __shfl_xor_sync(0xffffffffu, s[ni][0], off);
                    s[ni][1] += __shfl_xor_sync(0xffffffffu, s[ni][1], off);
                }
            }
            if (lane < 4) {
                float* dst = g_AGG + j * 32 + mb2 + 2 * ac;
                atomicAdd(dst + 0, s[0][0]);
                atomicAdd(dst + 1, s[0][1]);
                atomicAdd(dst + 8, s[1][0]);
                atomicAdd(dst + 9, s[1][1]);
            }
        }

        // H0 for next item (H0 free since the GEMM1->GEMM2 barrier)
        const int nxt = item + EGRID;
        if (nxt < NITEM)
            compute_H0(sH0w, nxt, w, lane,
                       wv, (const float4*)(g_B + (nxt >> 2) * H0D));
        __syncthreads();   // H0(next) visible; H1 free
        item = nxt;
    }
}

// ---------------------------------------------------------------------------
// k_node: 256 CTAs x 2 nodes, 256 threads. Node MLP + residual, fused
// projection (A/B for next edge pass), zero g_AGG.
// ---------------------------------------------------------------------------
__global__ void __launch_bounds__(256) k_node(
    const float* __restrict__ nw0, const float* __restrict__ nb0,
    const float* __restrict__ nw1, const float* __restrict__ nb1,
    const float* __restrict__ nw2, const float* __restrict__ nb2,
    const float* __restrict__ nwo, const float* __restrict__ nbo,
    const float* __restrict__ ew0, const float* __restrict__ eb0)
{
    __shared__ float sy[2 * 96], sh0[2 * 128], sh1[2 * 64], sh2[2 * 32], sNF[2 * 64];
    const int t = threadIdx.x;
    const int nb2_ = blockIdx.x * 2;

    if (t < 192) {
        int nd = t / 96, c = t % 96;
        sy[t] = (c < 64) ? g_NF[(nb2_ + nd) * 64 + c]
                         : g_AGG[(nb2_ + nd) * 32 + (c - 64)];
    }
    __syncthreads();
    if (t < 64) g_AGG[blockIdx.x * 64 + t] = 0.f;

    const int nd = t >> 7;
    const int o = t & 127;
    // layer 0: 96 -> 128  (2 x 128 = 256 outs)
    {
        float acc = __ldg(nb0 + o);
#pragma unroll 8
        for (int c = 0; c < 96; c++)
            acc = fmaf(sy[nd * 96 + c], __ldg(nw0 + c * 128 + o), acc);
        sh0[nd * 128 + o] = fmaxf(acc, 0.f);
    }
    __syncthreads();
    // layer 1: 128 -> 64  (2 x 64 = 128 active)
    if (t < 128) {
        const int n1 = t >> 6, o1 = t & 63;
        float acc = __ldg(nb1 + o1);
#pragma unroll 8
        for (int c = 0; c < 128; c++)
            acc = fmaf(sh0[n1 * 128 + c], __ldg(nw1 + c * 64 + o1), acc);
        sh1[n1 * 64 + o1] = fmaxf(acc, 0.f);
    }
    __syncthreads();
    // layer 2: 64 -> 32   (2 x 32 = 64 active)
    if (t < 64) {
        const int n2 = t >> 5, o2 = t & 31;
        float acc = __ldg(nb2 + o2);
#pragma unroll 8
        for (int c = 0; c < 64; c++)
            acc = fmaf(sh1[n2 * 64 + c], __ldg(nw2 + c * 32 + o2), acc);
        sh2[n2 * 32 + o2] = fmaxf(acc, 0.f);
    }
    __syncthreads();
    // output: 32 -> 64, residual (2 x 64 = 128 active)
    if (t < 128) {
        const int n3 = t >> 6, o3 = t & 63;
        float acc = __ldg(nbo + o3);
#pragma unroll 8
        for (int c = 0; c < 32; c++)
            acc = fmaf(sh2[n3 * 32 + c], __ldg(nwo + c * 64 + o3), acc);
        float y = sy[n3 * 96 + o3] + acc;
        g_NF[(nb2_ + n3) * 64 + o3] = y;
        sNF[n3 * 64 + o3] = y;
    }
    __syncthreads();
    // fused projection: A = nf@ew0[0:64], B = nf@ew0[64:128]+eb0
    {
        float a = 0.f, b = 0.f;
#pragma unroll 8
        for (int c = 0; c < 64; c++) {
            float v = sNF[nd * 64 + c];
            a = fmaf(v, __ldg(ew0 + c * 128 + o), a);
            b = fmaf(v, __ldg(ew0 + (64 + c) * 128 + o), b);
        }
        b += __ldg(eb0 + o);
        const int node = nb2_ + nd;
        g_A[node * 128 + o] = a;
        g_B[node * 128 + o] = b;
    }
}

// ---------------------------------------------------------------------------
__global__ void k_read(const float* __restrict__ rw, const float* __restrict__ rb,
                       float* __restrict__ out)
{
    int jn = blockIdx.x * blockDim.x + threadIdx.x;
    if (jn >= NN) return;
    float a0 = rb[0], a1 = rb[1], a2 = rb[2];
#pragma unroll
    for (int c = 0; c < 64; c++) {
        float v = g_NF[jn * FD + c];
        a0 = fmaf(v, rw[c * 3 + 0], a0);
        a1 = fmaf(v, rw[c * 3 + 1], a1);
        a2 = fmaf(v, rw[c * 3 + 2], a2);
    }
    out[jn * 3 + 0] = a0;
    out[jn * 3 + 1] = a1;
    out[jn * 3 + 2] = a2;
}

// ---------------------------------------------------------------------------
extern "C" void kernel_launch(void* const* d_in, const int* in_sizes, int n_in,
                              void* d_out, int out_size)
{
    const float* states = (const float*)d_in[0];
    const float* obj    = (const float*)d_in[1];
    const float* ew0 = (const float*)d_in[2];
    const float* eb0 = (const float*)d_in[3];
    const float* ew1 = (const float*)d_in[4];
    const float* eb1 = (const float*)d_in[5];
    const float* ew2 = (const float*)d_in[6];
    const float* eb2 = (const float*)d_in[7];
    const float* nw0 = (const float*)d_in[8];
    const float* nb0 = (const float*)d_in[9];
    const float* nw1 = (const float*)d_in[10];
    const float* nb1 = (const float*)d_in[11];
    const float* nw2 = (const float*)d_in[12];
    const float* nb2 = (const float*)d_in[13];
    const float* nwo = (const float*)d_in[14];
    const float* nbo = (const float*)d_in[15];
    const float* rw  = (const float*)d_in[16];
    const float* rb  = (const float*)d_in[17];
    float* out = (float*)d_out;

    cudaFuncSetAttribute(k_edge, cudaFuncAttributeMaxDynamicSharedMemorySize,
                         E_SMEMW * (int)sizeof(uint32_t));
    cudaFuncSetAttribute(k_proj, cudaFuncAttributeMaxDynamicSharedMemorySize,
                         PROJ_SMEM * (int)sizeof(float));

    // launch order keeps the 2nd k_edge at index 5 (ncu -s 5 -c 1 capture slot)
    k_init_nf<<<128, 256>>>(states, obj);
    k_init_dist<<<NN, 256>>>(states);
    k_proj<<<64, 256, PROJ_SMEM * (int)sizeof(float)>>>(ew0, eb0);
    for (int it = 0; it < 3; it++) {
        k_edge<<<EGRID, 256, E_SMEMW * (int)sizeof(uint32_t)>>>(ew0, ew1, eb1, ew2, eb2);
        k_node<<<256, 256>>>(nw0, nb0, nw1, nb1, nw2, nb2, nwo, nbo, ew0, eb0);
    }
    k_read<<<4, 128>>>(rw, rb, out);
}